// round 11
// baseline (speedup 1.0000x reference)
#include <cuda_runtime.h>

// GuidedFilter, causal box window R=20 (trailing, clamped prefix at edges), H then W.
// Stage1: box{I,p,Ip,I2} -> A,b (scratch).  Stage2: box{A,b} -> q.
//
// R11 = R9 (best: scalar hwindow, FMA split, bounds(128,5), __ldcs/__stcs,
// NBAND=16) + software pipelining: next row's main loads (new row + old row)
// are prefetched into registers while the current row computes, hiding L2/DRAM
// latency behind one loop iteration. Halo loads (5 lanes) remain in-loop.
// Arithmetic order unchanged -> bit-identical results to R9.

#define Hn 1024
#define Wn 1024
#define NIMG 24
#define R 20
#define NBAND 16
#define BANDH 64
#define TPB 128

__device__ float4 g_AB4[(size_t)NIMG * Hn * (Wn / 2)];

// Horizontal window of width 20 for 4 elements/lane; all shfls independent.
__device__ __forceinline__ void hwindow(const float v[4], const float hv[4],
                                        bool hasHalo, int lane, float w[4])
{
    const float p0 = v[0];
    const float p1 = __fadd_rn(p0, v[1]);
    const float p2 = __fadd_rn(p1, v[2]);
    const float p3 = __fadd_rn(p2, v[3]);
    const float T  = p3;

    const float t1 = __shfl_up_sync(0xffffffffu, T, 1);
    const float t2 = __shfl_up_sync(0xffffffffu, T, 2);
    const float t3 = __shfl_up_sync(0xffffffffu, T, 3);
    const float t4 = __shfl_up_sync(0xffffffffu, T, 4);
    const float t5 = __shfl_up_sync(0xffffffffu, T, 5);
    const float s0 = __shfl_up_sync(0xffffffffu, p0, 5);
    const float s1 = __shfl_up_sync(0xffffffffu, p1, 5);
    const float s2 = __shfl_up_sync(0xffffffffu, p2, 5);
    const float s3 = t5;                    // p3 == T

    float sumT = 0.0f;
    if (lane >= 1) sumT = __fadd_rn(sumT, t1);
    if (lane >= 2) sumT = __fadd_rn(sumT, t2);
    if (lane >= 3) sumT = __fadd_rn(sumT, t3);
    if (lane >= 4) sumT = __fadd_rn(sumT, t4);
    if (lane >= 5) sumT = __fadd_rn(sumT, t5);

    const float hp0 = hv[0];
    const float hp1 = __fadd_rn(hp0, hv[1]);
    const float hp2 = __fadd_rn(hp1, hv[2]);
    const float hp3 = __fadd_rn(hp2, hv[3]);
    const float d1 = __shfl_down_sync(0xffffffffu, hp3, 1);
    const float d2 = __shfl_down_sync(0xffffffffu, hp3, 2);
    const float d3 = __shfl_down_sync(0xffffffffu, hp3, 3);
    const float d4 = __shfl_down_sync(0xffffffffu, hp3, 4);
    float hs = 0.0f;
    if (lane <= 3) hs = __fadd_rn(hs, d1);
    if (lane <= 2) hs = __fadd_rn(hs, d2);
    if (lane <= 1) hs = __fadd_rn(hs, d3);
    if (lane == 0) hs = __fadd_rn(hs, d4);

    const float hq0 = __fsub_rn(hp3, hp0);
    const float hq1 = __fsub_rn(hp3, hp1);
    const float hq2 = __fsub_rn(hp3, hp2);

    const float c0_ = __fadd_rn(p0, sumT);
    const float c1_ = __fadd_rn(p1, sumT);
    const float c2_ = __fadd_rn(p2, sumT);
    const float c3_ = __fadd_rn(p3, sumT);

    if (lane >= 5) {
        w[0] = __fsub_rn(c0_, s0);
        w[1] = __fsub_rn(c1_, s1);
        w[2] = __fsub_rn(c2_, s2);
        w[3] = __fsub_rn(c3_, s3);
    } else if (hasHalo) {
        w[0] = __fadd_rn(__fadd_rn(c0_, hs), hq0);
        w[1] = __fadd_rn(__fadd_rn(c1_, hs), hq1);
        w[2] = __fadd_rn(__fadd_rn(c2_, hs), hq2);
        w[3] = __fadd_rn(c3_, hs);
    } else {
        w[0] = c0_;
        w[1] = c1_;
        w[2] = c2_;
        w[3] = c3_;
    }
}

__global__ void __launch_bounds__(TPB, 5)
gf_stage1(const float* __restrict__ gI, const float* __restrict__ gP)
{
    const int lane = threadIdx.x & 31;
    const int wid  = threadIdx.x >> 5;
    const int img  = blockIdx.z;
    const int c0   = (blockIdx.x * 4 + wid) * 128;
    const bool hasHalo = (c0 != 0);
    const int r0 = blockIdx.y * BANDH;
    const int r1 = r0 + BANDH;
    const int gstart = (r0 >= R - 1) ? (r0 - (R - 1)) : 0;
    const int subStart = gstart + R;

    const float4* I4  = (const float4*)(gI + (size_t)img * Hn * Wn);
    const float4* P4  = (const float4*)(gP + (size_t)img * Hn * Wn);
    float4* AB4 = g_AB4 + (size_t)img * Hn * (Wn / 2);

    const int mi = (c0 >> 2) + lane;
    const int hi = ((c0 - 20) >> 2) + lane;

    float vI[4]  = {0,0,0,0}, vP[4]  = {0,0,0,0};
    float vIP[4] = {0,0,0,0}, vII[4] = {0,0,0,0};
    float hI[4]  = {0,0,0,0}, hP[4]  = {0,0,0,0};
    float hIP[4] = {0,0,0,0}, hII[4] = {0,0,0,0};
    const float inv400 = 1.0f / 400.0f;
    const float4 zf4 = make_float4(0.f, 0.f, 0.f, 0.f);

    // preload row gstart (no old row there: subStart = gstart + R)
    float4 cIn = I4[(gstart << 8) + mi];
    float4 cPn = P4[(gstart << 8) + mi];
    float4 cIo = zf4, cPo = zf4;

    for (int gi = gstart; gi < r1; ++gi) {
        // ---- prefetch next row's main loads ----
        float4 nIn = zf4, nPn = zf4, nIo = zf4, nPo = zf4;
        const int gn = gi + 1;
        if (gn < r1) {
            const int nrbase = gn << 8;
            nIn = I4[nrbase + mi];
            nPn = P4[nrbase + mi];
            if (gn >= subStart) {
                const int nobase = (gn - R) << 8;
                nIo = __ldcs(I4 + nobase + mi);
                nPo = __ldcs(P4 + nobase + mi);
            }
        }

        // ---- halo loads for current row (5 lanes) ----
        float4 HIn = zf4, HPn = zf4, HIo = zf4, HPo = zf4;
        const bool doSub = (gi >= subStart);
        if (hasHalo && lane < 5) {
            const int rbase = gi << 8;
            HIn = I4[rbase + hi]; HPn = P4[rbase + hi];
            if (doSub) {
                const int obase = (gi - R) << 8;
                HIo = __ldcs(I4 + obase + hi); HPo = __ldcs(P4 + obase + hi);
            }
        }

        {
            const float in_[4] = {cIn.x, cIn.y, cIn.z, cIn.w};
            const float pn_[4] = {cPn.x, cPn.y, cPn.z, cPn.w};
            const float io_[4] = {cIo.x, cIo.y, cIo.z, cIo.w};
            const float po_[4] = {cPo.x, cPo.y, cPo.z, cPo.w};
            if (gi < R) {
                // exact sequential path (edge rows; ref-rounding bit-match)
#pragma unroll
                for (int e = 0; e < 4; ++e) {
                    vI[e]  = __fsub_rn(__fadd_rn(vI[e],  in_[e]), io_[e]);
                    vP[e]  = __fsub_rn(__fadd_rn(vP[e],  pn_[e]), po_[e]);
                    vIP[e] = __fsub_rn(__fadd_rn(vIP[e], __fmul_rn(in_[e], pn_[e])),
                                       __fmul_rn(io_[e], po_[e]));
                    vII[e] = __fsub_rn(__fadd_rn(vII[e], __fmul_rn(in_[e], in_[e])),
                                       __fmul_rn(io_[e], io_[e]));
                }
            } else {
#pragma unroll
                for (int e = 0; e < 4; ++e) {
                    vI[e]  = __fsub_rn(__fadd_rn(vI[e],  in_[e]), io_[e]);
                    vP[e]  = __fsub_rn(__fadd_rn(vP[e],  pn_[e]), po_[e]);
                    vIP[e] = fmaf(in_[e], pn_[e], fmaf(-io_[e], po_[e], vIP[e]));
                    vII[e] = fmaf(in_[e], in_[e], fmaf(-io_[e], io_[e], vII[e]));
                }
            }
        }
        if (hasHalo) {
            const float in_[4] = {HIn.x, HIn.y, HIn.z, HIn.w};
            const float pn_[4] = {HPn.x, HPn.y, HPn.z, HPn.w};
            const float io_[4] = {HIo.x, HIo.y, HIo.z, HIo.w};
            const float po_[4] = {HPo.x, HPo.y, HPo.z, HPo.w};
#pragma unroll
            for (int e = 0; e < 4; ++e) {
                hI[e]  = __fsub_rn(__fadd_rn(hI[e],  in_[e]), io_[e]);
                hP[e]  = __fsub_rn(__fadd_rn(hP[e],  pn_[e]), po_[e]);
                hIP[e] = fmaf(in_[e], pn_[e], fmaf(-io_[e], po_[e], hIP[e]));
                hII[e] = fmaf(in_[e], in_[e], fmaf(-io_[e], io_[e], hII[e]));
            }
        }

        if (gi >= r0) {
            float w0[4], w1[4], w2[4], w3[4];
            hwindow(vI,  hI,  hasHalo, lane, w0);
            hwindow(vP,  hP,  hasHalo, lane, w1);
            hwindow(vIP, hIP, hasHalo, lane, w2);
            hwindow(vII, hII, hasHalo, lane, w3);

            const bool divpath = (gi + 1 < R) || (!hasHalo && lane < 5);
            float A_[4], b_[4];
            if (divpath) {
                const float Nrf = (gi + 1 < R) ? (float)(gi + 1) : 20.0f;
#pragma unroll
                for (int e = 0; e < 4; ++e) {
                    const int colp1 = c0 + lane * 4 + e + 1;
                    const float Ncf = (colp1 < R) ? (float)colp1 : 20.0f;
                    const float Nf = __fmul_rn(Nrf, Ncf);
                    const float m0 = __fdiv_rn(w0[e], Nf);
                    const float m1 = __fdiv_rn(w1[e], Nf);
                    const float m2 = __fdiv_rn(w2[e], Nf);
                    const float m3 = __fdiv_rn(w3[e], Nf);
                    const float cov = __fsub_rn(m2, __fmul_rn(m0, m1));
                    const float var = __fsub_rn(m3, __fmul_rn(m0, m0));
                    A_[e] = __fdiv_rn(cov, __fadd_rn(var, 1e-8f));
                    b_[e] = __fsub_rn(m1, __fmul_rn(A_[e], m0));
                }
            } else {
#pragma unroll
                for (int e = 0; e < 4; ++e) {
                    const float m0 = w0[e] * inv400;
                    const float m1 = w1[e] * inv400;
                    const float m2 = w2[e] * inv400;
                    const float m3 = w3[e] * inv400;
                    const float cov = fmaf(-m0, m1, m2);
                    const float var = fmaf(-m0, m0, m3);
                    const float A = __fdividef(cov, var + 1e-8f);
                    A_[e] = A;
                    b_[e] = fmaf(-A, m0, m1);
                }
            }
            const int sbase = gi * (Wn / 2) + (c0 >> 1) + lane * 2;
            __stcs(AB4 + sbase,     make_float4(A_[0], b_[0], A_[1], b_[1]));
            __stcs(AB4 + sbase + 1, make_float4(A_[2], b_[2], A_[3], b_[3]));
        }

        cIn = nIn; cPn = nPn; cIo = nIo; cPo = nPo;
    }
}

__global__ void __launch_bounds__(TPB, 5)
gf_stage2(const float* __restrict__ gI, float* __restrict__ gQ)
{
    const int lane = threadIdx.x & 31;
    const int wid  = threadIdx.x >> 5;
    const int img  = blockIdx.z;
    const int c0   = (blockIdx.x * 4 + wid) * 128;
    const bool hasHalo = (c0 != 0);
    const int r0 = blockIdx.y * BANDH;
    const int r1 = r0 + BANDH;
    const int gstart = (r0 >= R - 1) ? (r0 - (R - 1)) : 0;
    const int subStart = gstart + R;

    const float4* I4  = (const float4*)(gI + (size_t)img * Hn * Wn);
    const float4* AB4 = g_AB4 + (size_t)img * Hn * (Wn / 2);
    float4* Q4 = (float4*)(gQ + (size_t)img * Hn * Wn);

    const int mi = (c0 >> 2) + lane;
    const int ai = (c0 >> 1) + lane * 2;
    const int hai = ((c0 - 20) >> 1) + lane * 2;

    float vA[4] = {0,0,0,0}, vB[4] = {0,0,0,0};
    float hA[4] = {0,0,0,0}, hB[4] = {0,0,0,0};
    const float inv400 = 1.0f / 400.0f;
    const float4 zf4 = make_float4(0.f, 0.f, 0.f, 0.f);

    // preload row gstart
    float4 cu0 = AB4[gstart * (Wn / 2) + ai];
    float4 cu1 = AB4[gstart * (Wn / 2) + ai + 1];
    float4 co0 = zf4, co1 = zf4;

    for (int gi = gstart; gi < r1; ++gi) {
        // ---- prefetch next row's main loads ----
        float4 nu0 = zf4, nu1 = zf4, no0 = zf4, no1 = zf4;
        const int gn = gi + 1;
        if (gn < r1) {
            const int nabase = gn * (Wn / 2);
            nu0 = AB4[nabase + ai];
            nu1 = AB4[nabase + ai + 1];
            if (gn >= subStart) {
                const int nobase = (gn - R) * (Wn / 2);
                no0 = __ldcs(AB4 + nobase + ai);
                no1 = __ldcs(AB4 + nobase + ai + 1);
            }
        }

        // ---- halo loads for current row (5 lanes) ----
        float4 hu0 = zf4, hu1 = zf4, ho0 = zf4, ho1 = zf4;
        const bool doSub = (gi >= subStart);
        if (hasHalo && lane < 5) {
            const int abase = gi * (Wn / 2);
            hu0 = AB4[abase + hai]; hu1 = AB4[abase + hai + 1];
            if (doSub) {
                const int obase = (gi - R) * (Wn / 2);
                ho0 = __ldcs(AB4 + obase + hai); ho1 = __ldcs(AB4 + obase + hai + 1);
            }
        }

        {
            const float an[4] = {cu0.x, cu0.z, cu1.x, cu1.z};
            const float bn[4] = {cu0.y, cu0.w, cu1.y, cu1.w};
            const float ao[4] = {co0.x, co0.z, co1.x, co1.z};
            const float bo[4] = {co0.y, co0.w, co1.y, co1.w};
#pragma unroll
            for (int e = 0; e < 4; ++e) {
                vA[e] = __fsub_rn(__fadd_rn(vA[e], an[e]), ao[e]);
                vB[e] = __fsub_rn(__fadd_rn(vB[e], bn[e]), bo[e]);
            }
        }
        if (hasHalo) {
            const float an[4] = {hu0.x, hu0.z, hu1.x, hu1.z};
            const float bn[4] = {hu0.y, hu0.w, hu1.y, hu1.w};
            const float ao[4] = {ho0.x, ho0.z, ho1.x, ho1.z};
            const float bo[4] = {ho0.y, ho0.w, ho1.y, ho1.w};
#pragma unroll
            for (int e = 0; e < 4; ++e) {
                hA[e] = __fsub_rn(__fadd_rn(hA[e], an[e]), ao[e]);
                hB[e] = __fsub_rn(__fadd_rn(hB[e], bn[e]), bo[e]);
            }
        }

        if (gi >= r0) {
            float wA[4], wB[4];
            hwindow(vA, hA, hasHalo, lane, wA);
            hwindow(vB, hB, hasHalo, lane, wB);

            const bool divpath = (gi + 1 < R) || (!hasHalo && lane < 5);
            const float4 Iv = __ldcs(I4 + (gi << 8) + mi);
            const float iv_[4] = {Iv.x, Iv.y, Iv.z, Iv.w};
            float q_[4];
            if (divpath) {
                const float Nrf = (gi + 1 < R) ? (float)(gi + 1) : 20.0f;
#pragma unroll
                for (int e = 0; e < 4; ++e) {
                    const int colp1 = c0 + lane * 4 + e + 1;
                    const float Ncf = (colp1 < R) ? (float)colp1 : 20.0f;
                    const float Nf = __fmul_rn(Nrf, Ncf);
                    const float mA = __fdiv_rn(wA[e], Nf);
                    const float mB = __fdiv_rn(wB[e], Nf);
                    q_[e] = __fadd_rn(__fmul_rn(mA, iv_[e]), mB);
                }
            } else {
#pragma unroll
                for (int e = 0; e < 4; ++e) {
                    const float mA = wA[e] * inv400;
                    const float mB = wB[e] * inv400;
                    q_[e] = fmaf(mA, iv_[e], mB);
                }
            }
            __stcs(Q4 + (gi << 8) + mi, make_float4(q_[0], q_[1], q_[2], q_[3]));
        }

        cu0 = nu0; cu1 = nu1; co0 = no0; co1 = no1;
    }
}

extern "C" void kernel_launch(void* const* d_in, const int* in_sizes, int n_in,
                              void* d_out, int out_size)
{
    (void)in_sizes; (void)n_in; (void)out_size;
    const float* I = (const float*)d_in[0];
    const float* p = (const float*)d_in[1];
    float* q = (float*)d_out;

    dim3 grid(2, NBAND, NIMG);
    gf_stage1<<<grid, TPB>>>(I, p);
    gf_stage2<<<grid, TPB>>>(I, q);
}

// round 12
// speedup vs baseline: 1.2356x; 1.2356x over previous
#include <cuda_runtime.h>

// GuidedFilter, causal box window R=20 (trailing, clamped prefix at edges), H then W.
// Stage1: box{I,p,Ip,I2} -> A,b (scratch).  Stage2: box{A,b} -> q.
//
// R12 = R9 (best: scalar hwindow, FMA split, __ldcs/__stcs, NBAND=16) with
// __launch_bounds__(128, 6) on BOTH kernels: 768 CTAs fit in ONE wave
// (6 x 148 = 888 >= 768) and 24 warps/SM instead of 20 hide L2 latency.
// R9 uses 76 regs <= 85-reg cap at occupancy 6 -> no spills expected.

#define Hn 1024
#define Wn 1024
#define NIMG 24
#define R 20
#define NBAND 16
#define BANDH 64
#define TPB 128

__device__ float4 g_AB4[(size_t)NIMG * Hn * (Wn / 2)];

// Horizontal window of width 20 for 4 elements/lane; all shfls independent.
__device__ __forceinline__ void hwindow(const float v[4], const float hv[4],
                                        bool hasHalo, int lane, float w[4])
{
    const float p0 = v[0];
    const float p1 = __fadd_rn(p0, v[1]);
    const float p2 = __fadd_rn(p1, v[2]);
    const float p3 = __fadd_rn(p2, v[3]);
    const float T  = p3;

    const float t1 = __shfl_up_sync(0xffffffffu, T, 1);
    const float t2 = __shfl_up_sync(0xffffffffu, T, 2);
    const float t3 = __shfl_up_sync(0xffffffffu, T, 3);
    const float t4 = __shfl_up_sync(0xffffffffu, T, 4);
    const float t5 = __shfl_up_sync(0xffffffffu, T, 5);
    const float s0 = __shfl_up_sync(0xffffffffu, p0, 5);
    const float s1 = __shfl_up_sync(0xffffffffu, p1, 5);
    const float s2 = __shfl_up_sync(0xffffffffu, p2, 5);
    const float s3 = t5;                    // p3 == T

    float sumT = 0.0f;
    if (lane >= 1) sumT = __fadd_rn(sumT, t1);
    if (lane >= 2) sumT = __fadd_rn(sumT, t2);
    if (lane >= 3) sumT = __fadd_rn(sumT, t3);
    if (lane >= 4) sumT = __fadd_rn(sumT, t4);
    if (lane >= 5) sumT = __fadd_rn(sumT, t5);

    const float hp0 = hv[0];
    const float hp1 = __fadd_rn(hp0, hv[1]);
    const float hp2 = __fadd_rn(hp1, hv[2]);
    const float hp3 = __fadd_rn(hp2, hv[3]);
    const float d1 = __shfl_down_sync(0xffffffffu, hp3, 1);
    const float d2 = __shfl_down_sync(0xffffffffu, hp3, 2);
    const float d3 = __shfl_down_sync(0xffffffffu, hp3, 3);
    const float d4 = __shfl_down_sync(0xffffffffu, hp3, 4);
    float hs = 0.0f;
    if (lane <= 3) hs = __fadd_rn(hs, d1);
    if (lane <= 2) hs = __fadd_rn(hs, d2);
    if (lane <= 1) hs = __fadd_rn(hs, d3);
    if (lane == 0) hs = __fadd_rn(hs, d4);

    const float hq0 = __fsub_rn(hp3, hp0);
    const float hq1 = __fsub_rn(hp3, hp1);
    const float hq2 = __fsub_rn(hp3, hp2);

    const float c0_ = __fadd_rn(p0, sumT);
    const float c1_ = __fadd_rn(p1, sumT);
    const float c2_ = __fadd_rn(p2, sumT);
    const float c3_ = __fadd_rn(p3, sumT);

    if (lane >= 5) {
        w[0] = __fsub_rn(c0_, s0);
        w[1] = __fsub_rn(c1_, s1);
        w[2] = __fsub_rn(c2_, s2);
        w[3] = __fsub_rn(c3_, s3);
    } else if (hasHalo) {
        w[0] = __fadd_rn(__fadd_rn(c0_, hs), hq0);
        w[1] = __fadd_rn(__fadd_rn(c1_, hs), hq1);
        w[2] = __fadd_rn(__fadd_rn(c2_, hs), hq2);
        w[3] = __fadd_rn(c3_, hs);
    } else {
        w[0] = c0_;
        w[1] = c1_;
        w[2] = c2_;
        w[3] = c3_;
    }
}

__global__ void __launch_bounds__(TPB, 6)
gf_stage1(const float* __restrict__ gI, const float* __restrict__ gP)
{
    const int lane = threadIdx.x & 31;
    const int wid  = threadIdx.x >> 5;
    const int img  = blockIdx.z;
    const int c0   = (blockIdx.x * 4 + wid) * 128;
    const bool hasHalo = (c0 != 0);
    const int r0 = blockIdx.y * BANDH;
    const int r1 = r0 + BANDH;
    const int gstart = (r0 >= R - 1) ? (r0 - (R - 1)) : 0;
    const int subStart = gstart + R;

    const float4* I4  = (const float4*)(gI + (size_t)img * Hn * Wn);
    const float4* P4  = (const float4*)(gP + (size_t)img * Hn * Wn);
    float4* AB4 = g_AB4 + (size_t)img * Hn * (Wn / 2);

    const int mi = (c0 >> 2) + lane;
    const int hi = ((c0 - 20) >> 2) + lane;

    float vI[4]  = {0,0,0,0}, vP[4]  = {0,0,0,0};
    float vIP[4] = {0,0,0,0}, vII[4] = {0,0,0,0};
    float hI[4]  = {0,0,0,0}, hP[4]  = {0,0,0,0};
    float hIP[4] = {0,0,0,0}, hII[4] = {0,0,0,0};
    const float inv400 = 1.0f / 400.0f;

    for (int gi = gstart; gi < r1; ++gi) {
        const int rbase = gi << 8;
        const float4 In = I4[rbase + mi];       // reused as 'old' within 20 rows: keep in L2
        const float4 Pn = P4[rbase + mi];
        float4 Io = make_float4(0.f,0.f,0.f,0.f), Po = Io;
        float4 HIn = Io, HPn = Io, HIo = Io, HPo = Io;
        const bool doSub = (gi >= subStart);
        const int obase = (gi - R) << 8;
        if (doSub) { Io = __ldcs(I4 + obase + mi); Po = __ldcs(P4 + obase + mi); }
        if (hasHalo && lane < 5) {
            HIn = I4[rbase + hi]; HPn = P4[rbase + hi];
            if (doSub) { HIo = __ldcs(I4 + obase + hi); HPo = __ldcs(P4 + obase + hi); }
        }

        {
            const float in_[4] = {In.x, In.y, In.z, In.w};
            const float pn_[4] = {Pn.x, Pn.y, Pn.z, Pn.w};
            const float io_[4] = {Io.x, Io.y, Io.z, Io.w};
            const float po_[4] = {Po.x, Po.y, Po.z, Po.w};
            if (gi < R) {
                // exact sequential path (edge rows; ref-rounding bit-match)
#pragma unroll
                for (int e = 0; e < 4; ++e) {
                    vI[e]  = __fsub_rn(__fadd_rn(vI[e],  in_[e]), io_[e]);
                    vP[e]  = __fsub_rn(__fadd_rn(vP[e],  pn_[e]), po_[e]);
                    vIP[e] = __fsub_rn(__fadd_rn(vIP[e], __fmul_rn(in_[e], pn_[e])),
                                       __fmul_rn(io_[e], po_[e]));
                    vII[e] = __fsub_rn(__fadd_rn(vII[e], __fmul_rn(in_[e], in_[e])),
                                       __fmul_rn(io_[e], io_[e]));
                }
            } else {
#pragma unroll
                for (int e = 0; e < 4; ++e) {
                    vI[e]  = __fsub_rn(__fadd_rn(vI[e],  in_[e]), io_[e]);
                    vP[e]  = __fsub_rn(__fadd_rn(vP[e],  pn_[e]), po_[e]);
                    vIP[e] = fmaf(in_[e], pn_[e], fmaf(-io_[e], po_[e], vIP[e]));
                    vII[e] = fmaf(in_[e], in_[e], fmaf(-io_[e], io_[e], vII[e]));
                }
            }
        }
        if (hasHalo) {
            // halo feeds only cols >= 108 (well-conditioned): FMA always
            const float in_[4] = {HIn.x, HIn.y, HIn.z, HIn.w};
            const float pn_[4] = {HPn.x, HPn.y, HPn.z, HPn.w};
            const float io_[4] = {HIo.x, HIo.y, HIo.z, HIo.w};
            const float po_[4] = {HPo.x, HPo.y, HPo.z, HPo.w};
#pragma unroll
            for (int e = 0; e < 4; ++e) {
                hI[e]  = __fsub_rn(__fadd_rn(hI[e],  in_[e]), io_[e]);
                hP[e]  = __fsub_rn(__fadd_rn(hP[e],  pn_[e]), po_[e]);
                hIP[e] = fmaf(in_[e], pn_[e], fmaf(-io_[e], po_[e], hIP[e]));
                hII[e] = fmaf(in_[e], in_[e], fmaf(-io_[e], io_[e], hII[e]));
            }
        }

        if (gi >= r0) {
            float w0[4], w1[4], w2[4], w3[4];
            hwindow(vI,  hI,  hasHalo, lane, w0);
            hwindow(vP,  hP,  hasHalo, lane, w1);
            hwindow(vIP, hIP, hasHalo, lane, w2);
            hwindow(vII, hII, hasHalo, lane, w3);

            const bool divpath = (gi + 1 < R) || (!hasHalo && lane < 5);
            float A_[4], b_[4];
            if (divpath) {
                const float Nrf = (gi + 1 < R) ? (float)(gi + 1) : 20.0f;
#pragma unroll
                for (int e = 0; e < 4; ++e) {
                    const int colp1 = c0 + lane * 4 + e + 1;
                    const float Ncf = (colp1 < R) ? (float)colp1 : 20.0f;
                    const float Nf = __fmul_rn(Nrf, Ncf);
                    const float m0 = __fdiv_rn(w0[e], Nf);
                    const float m1 = __fdiv_rn(w1[e], Nf);
                    const float m2 = __fdiv_rn(w2[e], Nf);
                    const float m3 = __fdiv_rn(w3[e], Nf);
                    const float cov = __fsub_rn(m2, __fmul_rn(m0, m1));
                    const float var = __fsub_rn(m3, __fmul_rn(m0, m0));
                    A_[e] = __fdiv_rn(cov, __fadd_rn(var, 1e-8f));
                    b_[e] = __fsub_rn(m1, __fmul_rn(A_[e], m0));
                }
            } else {
#pragma unroll
                for (int e = 0; e < 4; ++e) {
                    const float m0 = w0[e] * inv400;
                    const float m1 = w1[e] * inv400;
                    const float m2 = w2[e] * inv400;
                    const float m3 = w3[e] * inv400;
                    const float cov = fmaf(-m0, m1, m2);
                    const float var = fmaf(-m0, m0, m3);
                    const float A = __fdividef(cov, var + 1e-8f);
                    A_[e] = A;
                    b_[e] = fmaf(-A, m0, m1);
                }
            }
            const int sbase = gi * (Wn / 2) + (c0 >> 1) + lane * 2;
            __stcs(AB4 + sbase,     make_float4(A_[0], b_[0], A_[1], b_[1]));
            __stcs(AB4 + sbase + 1, make_float4(A_[2], b_[2], A_[3], b_[3]));
        }
    }
}

__global__ void __launch_bounds__(TPB, 6)
gf_stage2(const float* __restrict__ gI, float* __restrict__ gQ)
{
    const int lane = threadIdx.x & 31;
    const int wid  = threadIdx.x >> 5;
    const int img  = blockIdx.z;
    const int c0   = (blockIdx.x * 4 + wid) * 128;
    const bool hasHalo = (c0 != 0);
    const int r0 = blockIdx.y * BANDH;
    const int r1 = r0 + BANDH;
    const int gstart = (r0 >= R - 1) ? (r0 - (R - 1)) : 0;
    const int subStart = gstart + R;

    const float4* I4  = (const float4*)(gI + (size_t)img * Hn * Wn);
    const float4* AB4 = g_AB4 + (size_t)img * Hn * (Wn / 2);
    float4* Q4 = (float4*)(gQ + (size_t)img * Hn * Wn);

    const int mi = (c0 >> 2) + lane;
    const int ai = (c0 >> 1) + lane * 2;
    const int hai = ((c0 - 20) >> 1) + lane * 2;

    float vA[4] = {0,0,0,0}, vB[4] = {0,0,0,0};
    float hA[4] = {0,0,0,0}, hB[4] = {0,0,0,0};
    const float inv400 = 1.0f / 400.0f;

    for (int gi = gstart; gi < r1; ++gi) {
        const int abase = gi * (Wn / 2);
        const float4 u0 = AB4[abase + ai];      // reused as 'old' within 20 rows: keep in L2
        const float4 u1 = AB4[abase + ai + 1];
        float4 o0 = make_float4(0.f,0.f,0.f,0.f), o1 = o0;
        float4 hu0 = o0, hu1 = o0, ho0 = o0, ho1 = o0;
        const bool doSub = (gi >= subStart);
        const int obase = (gi - R) * (Wn / 2);
        if (doSub) { o0 = __ldcs(AB4 + obase + ai); o1 = __ldcs(AB4 + obase + ai + 1); }
        if (hasHalo && lane < 5) {
            hu0 = AB4[abase + hai]; hu1 = AB4[abase + hai + 1];
            if (doSub) { ho0 = __ldcs(AB4 + obase + hai); ho1 = __ldcs(AB4 + obase + hai + 1); }
        }

        {
            const float an[4] = {u0.x, u0.z, u1.x, u1.z};
            const float bn[4] = {u0.y, u0.w, u1.y, u1.w};
            const float ao[4] = {o0.x, o0.z, o1.x, o1.z};
            const float bo[4] = {o0.y, o0.w, o1.y, o1.w};
#pragma unroll
            for (int e = 0; e < 4; ++e) {
                vA[e] = __fsub_rn(__fadd_rn(vA[e], an[e]), ao[e]);
                vB[e] = __fsub_rn(__fadd_rn(vB[e], bn[e]), bo[e]);
            }
        }
        if (hasHalo) {
            const float an[4] = {hu0.x, hu0.z, hu1.x, hu1.z};
            const float bn[4] = {hu0.y, hu0.w, hu1.y, hu1.w};
            const float ao[4] = {ho0.x, ho0.z, ho1.x, ho1.z};
            const float bo[4] = {ho0.y, ho0.w, ho1.y, ho1.w};
#pragma unroll
            for (int e = 0; e < 4; ++e) {
                hA[e] = __fsub_rn(__fadd_rn(hA[e], an[e]), ao[e]);
                hB[e] = __fsub_rn(__fadd_rn(hB[e], bn[e]), bo[e]);
            }
        }

        if (gi >= r0) {
            float wA[4], wB[4];
            hwindow(vA, hA, hasHalo, lane, wA);
            hwindow(vB, hB, hasHalo, lane, wB);

            const bool divpath = (gi + 1 < R) || (!hasHalo && lane < 5);
            const float4 Iv = __ldcs(I4 + (gi << 8) + mi);
            const float iv_[4] = {Iv.x, Iv.y, Iv.z, Iv.w};
            float q_[4];
            if (divpath) {
                const float Nrf = (gi + 1 < R) ? (float)(gi + 1) : 20.0f;
#pragma unroll
                for (int e = 0; e < 4; ++e) {
                    const int colp1 = c0 + lane * 4 + e + 1;
                    const float Ncf = (colp1 < R) ? (float)colp1 : 20.0f;
                    const float Nf = __fmul_rn(Nrf, Ncf);
                    const float mA = __fdiv_rn(wA[e], Nf);
                    const float mB = __fdiv_rn(wB[e], Nf);
                    q_[e] = __fadd_rn(__fmul_rn(mA, iv_[e]), mB);
                }
            } else {
#pragma unroll
                for (int e = 0; e < 4; ++e) {
                    const float mA = wA[e] * inv400;
                    const float mB = wB[e] * inv400;
                    q_[e] = fmaf(mA, iv_[e], mB);
                }
            }
            __stcs(Q4 + (gi << 8) + mi, make_float4(q_[0], q_[1], q_[2], q_[3]));
        }
    }
}

extern "C" void kernel_launch(void* const* d_in, const int* in_sizes, int n_in,
                              void* d_out, int out_size)
{
    (void)in_sizes; (void)n_in; (void)out_size;
    const float* I = (const float*)d_in[0];
    const float* p = (const float*)d_in[1];
    float* q = (float*)d_out;

    dim3 grid(2, NBAND, NIMG);
    gf_stage1<<<grid, TPB>>>(I, p);
    gf_stage2<<<grid, TPB>>>(I, q);
}

// round 13
// speedup vs baseline: 1.2658x; 1.0245x over previous
#include <cuda_runtime.h>

// GuidedFilter, causal box window R=20 (trailing, clamped prefix at edges), H then W.
// Stage1: box{I,p,Ip,I2} -> A,b (scratch).  Stage2: box{A,b} -> q.
//
// R13 composition of per-stage bests:
//  stage1 = R9: scalar hwindow, FMA split, bounds(128,5), __ldcs/__stcs.
//  stage2 = R8: scalar accumulators, f32x2-packed hwindow2 (packed only at the
//           call site: 8 pk2 movs buy a 2x cut in window FADDs; per-field
//           IEEE-rn => bit-identical), bounds(128,6), __ldcs/__stcs.

#define Hn 1024
#define Wn 1024
#define NIMG 24
#define R 20
#define NBAND 16
#define BANDH 64
#define TPB 128

typedef unsigned long long u64t;

__device__ float4 g_AB4[(size_t)NIMG * Hn * (Wn / 2)];

__device__ __forceinline__ u64t pk2(float lo, float hi) {
    u64t r; asm("mov.b64 %0,{%1,%2};" : "=l"(r) : "f"(lo), "f"(hi)); return r;
}
__device__ __forceinline__ float lo2(u64t v) {
    float a; asm("{ .reg .f32 h; mov.b64 {%0,h}, %1; }" : "=f"(a) : "l"(v)); return a;
}
__device__ __forceinline__ float hi2(u64t v) {
    float b; asm("{ .reg .f32 l; mov.b64 {l,%0}, %1; }" : "=f"(b) : "l"(v)); return b;
}
__device__ __forceinline__ u64t add2(u64t a, u64t b) {
    u64t r; asm("add.rn.f32x2 %0,%1,%2;" : "=l"(r) : "l"(a), "l"(b)); return r;
}
__device__ __forceinline__ u64t sub2(u64t a, u64t b) {   // rn(a-b) per field
    u64t r; const u64t n1 = 0xBF800000BF800000ULL;
    asm("fma.rn.f32x2 %0,%1,%2,%3;" : "=l"(r) : "l"(b), "l"(n1), "l"(a)); return r;
}

// ---------------- scalar hwindow (stage1) ----------------
__device__ __forceinline__ void hwindow(const float v[4], const float hv[4],
                                        bool hasHalo, int lane, float w[4])
{
    const float p0 = v[0];
    const float p1 = __fadd_rn(p0, v[1]);
    const float p2 = __fadd_rn(p1, v[2]);
    const float p3 = __fadd_rn(p2, v[3]);
    const float T  = p3;

    const float t1 = __shfl_up_sync(0xffffffffu, T, 1);
    const float t2 = __shfl_up_sync(0xffffffffu, T, 2);
    const float t3 = __shfl_up_sync(0xffffffffu, T, 3);
    const float t4 = __shfl_up_sync(0xffffffffu, T, 4);
    const float t5 = __shfl_up_sync(0xffffffffu, T, 5);
    const float s0 = __shfl_up_sync(0xffffffffu, p0, 5);
    const float s1 = __shfl_up_sync(0xffffffffu, p1, 5);
    const float s2 = __shfl_up_sync(0xffffffffu, p2, 5);
    const float s3 = t5;                    // p3 == T

    float sumT = 0.0f;
    if (lane >= 1) sumT = __fadd_rn(sumT, t1);
    if (lane >= 2) sumT = __fadd_rn(sumT, t2);
    if (lane >= 3) sumT = __fadd_rn(sumT, t3);
    if (lane >= 4) sumT = __fadd_rn(sumT, t4);
    if (lane >= 5) sumT = __fadd_rn(sumT, t5);

    const float hp0 = hv[0];
    const float hp1 = __fadd_rn(hp0, hv[1]);
    const float hp2 = __fadd_rn(hp1, hv[2]);
    const float hp3 = __fadd_rn(hp2, hv[3]);
    const float d1 = __shfl_down_sync(0xffffffffu, hp3, 1);
    const float d2 = __shfl_down_sync(0xffffffffu, hp3, 2);
    const float d3 = __shfl_down_sync(0xffffffffu, hp3, 3);
    const float d4 = __shfl_down_sync(0xffffffffu, hp3, 4);
    float hs = 0.0f;
    if (lane <= 3) hs = __fadd_rn(hs, d1);
    if (lane <= 2) hs = __fadd_rn(hs, d2);
    if (lane <= 1) hs = __fadd_rn(hs, d3);
    if (lane == 0) hs = __fadd_rn(hs, d4);

    const float hq0 = __fsub_rn(hp3, hp0);
    const float hq1 = __fsub_rn(hp3, hp1);
    const float hq2 = __fsub_rn(hp3, hp2);

    const float c0_ = __fadd_rn(p0, sumT);
    const float c1_ = __fadd_rn(p1, sumT);
    const float c2_ = __fadd_rn(p2, sumT);
    const float c3_ = __fadd_rn(p3, sumT);

    if (lane >= 5) {
        w[0] = __fsub_rn(c0_, s0);
        w[1] = __fsub_rn(c1_, s1);
        w[2] = __fsub_rn(c2_, s2);
        w[3] = __fsub_rn(c3_, s3);
    } else if (hasHalo) {
        w[0] = __fadd_rn(__fadd_rn(c0_, hs), hq0);
        w[1] = __fadd_rn(__fadd_rn(c1_, hs), hq1);
        w[2] = __fadd_rn(__fadd_rn(c2_, hs), hq2);
        w[3] = __fadd_rn(c3_, hs);
    } else {
        w[0] = c0_;
        w[1] = c1_;
        w[2] = c2_;
        w[3] = c3_;
    }
}

// ---------------- packed hwindow (stage2) ----------------
__device__ __forceinline__ void hwindow2(const u64t v[4], const u64t hv[4],
                                         bool hasHalo, int lane, u64t w[4])
{
    const u64t p0 = v[0];
    const u64t p1 = add2(p0, v[1]);
    const u64t p2 = add2(p1, v[2]);
    const u64t p3 = add2(p2, v[3]);
    const u64t T  = p3;

    const u64t t1 = __shfl_up_sync(0xffffffffu, T, 1);
    const u64t t2 = __shfl_up_sync(0xffffffffu, T, 2);
    const u64t t3 = __shfl_up_sync(0xffffffffu, T, 3);
    const u64t t4 = __shfl_up_sync(0xffffffffu, T, 4);
    const u64t t5 = __shfl_up_sync(0xffffffffu, T, 5);
    const u64t s0 = __shfl_up_sync(0xffffffffu, p0, 5);
    const u64t s1 = __shfl_up_sync(0xffffffffu, p1, 5);
    const u64t s2 = __shfl_up_sync(0xffffffffu, p2, 5);
    const u64t s3 = t5;

    u64t sumT = 0ULL;
    if (lane >= 1) sumT = add2(sumT, t1);
    if (lane >= 2) sumT = add2(sumT, t2);
    if (lane >= 3) sumT = add2(sumT, t3);
    if (lane >= 4) sumT = add2(sumT, t4);
    if (lane >= 5) sumT = add2(sumT, t5);

    const u64t hp0 = hv[0];
    const u64t hp1 = add2(hp0, hv[1]);
    const u64t hp2 = add2(hp1, hv[2]);
    const u64t hp3 = add2(hp2, hv[3]);
    const u64t d1 = __shfl_down_sync(0xffffffffu, hp3, 1);
    const u64t d2 = __shfl_down_sync(0xffffffffu, hp3, 2);
    const u64t d3 = __shfl_down_sync(0xffffffffu, hp3, 3);
    const u64t d4 = __shfl_down_sync(0xffffffffu, hp3, 4);
    u64t hs = 0ULL;
    if (lane <= 3) hs = add2(hs, d1);
    if (lane <= 2) hs = add2(hs, d2);
    if (lane <= 1) hs = add2(hs, d3);
    if (lane == 0) hs = add2(hs, d4);

    const u64t hq0 = sub2(hp3, hp0);
    const u64t hq1 = sub2(hp3, hp1);
    const u64t hq2 = sub2(hp3, hp2);

    const u64t c0_ = add2(p0, sumT);
    const u64t c1_ = add2(p1, sumT);
    const u64t c2_ = add2(p2, sumT);
    const u64t c3_ = add2(p3, sumT);

    if (lane >= 5) {
        w[0] = sub2(c0_, s0);
        w[1] = sub2(c1_, s1);
        w[2] = sub2(c2_, s2);
        w[3] = sub2(c3_, s3);
    } else if (hasHalo) {
        w[0] = add2(add2(c0_, hs), hq0);
        w[1] = add2(add2(c1_, hs), hq1);
        w[2] = add2(add2(c2_, hs), hq2);
        w[3] = add2(c3_, hs);
    } else {
        w[0] = c0_;
        w[1] = c1_;
        w[2] = c2_;
        w[3] = c3_;
    }
}

__global__ void __launch_bounds__(TPB, 5)
gf_stage1(const float* __restrict__ gI, const float* __restrict__ gP)
{
    const int lane = threadIdx.x & 31;
    const int wid  = threadIdx.x >> 5;
    const int img  = blockIdx.z;
    const int c0   = (blockIdx.x * 4 + wid) * 128;
    const bool hasHalo = (c0 != 0);
    const int r0 = blockIdx.y * BANDH;
    const int r1 = r0 + BANDH;
    const int gstart = (r0 >= R - 1) ? (r0 - (R - 1)) : 0;
    const int subStart = gstart + R;

    const float4* I4  = (const float4*)(gI + (size_t)img * Hn * Wn);
    const float4* P4  = (const float4*)(gP + (size_t)img * Hn * Wn);
    float4* AB4 = g_AB4 + (size_t)img * Hn * (Wn / 2);

    const int mi = (c0 >> 2) + lane;
    const int hi = ((c0 - 20) >> 2) + lane;

    float vI[4]  = {0,0,0,0}, vP[4]  = {0,0,0,0};
    float vIP[4] = {0,0,0,0}, vII[4] = {0,0,0,0};
    float hI[4]  = {0,0,0,0}, hP[4]  = {0,0,0,0};
    float hIP[4] = {0,0,0,0}, hII[4] = {0,0,0,0};
    const float inv400 = 1.0f / 400.0f;

    for (int gi = gstart; gi < r1; ++gi) {
        const int rbase = gi << 8;
        const float4 In = I4[rbase + mi];       // reused as 'old' within 20 rows: keep in L2
        const float4 Pn = P4[rbase + mi];
        float4 Io = make_float4(0.f,0.f,0.f,0.f), Po = Io;
        float4 HIn = Io, HPn = Io, HIo = Io, HPo = Io;
        const bool doSub = (gi >= subStart);
        const int obase = (gi - R) << 8;
        if (doSub) { Io = __ldcs(I4 + obase + mi); Po = __ldcs(P4 + obase + mi); }
        if (hasHalo && lane < 5) {
            HIn = I4[rbase + hi]; HPn = P4[rbase + hi];
            if (doSub) { HIo = __ldcs(I4 + obase + hi); HPo = __ldcs(P4 + obase + hi); }
        }

        {
            const float in_[4] = {In.x, In.y, In.z, In.w};
            const float pn_[4] = {Pn.x, Pn.y, Pn.z, Pn.w};
            const float io_[4] = {Io.x, Io.y, Io.z, Io.w};
            const float po_[4] = {Po.x, Po.y, Po.z, Po.w};
            if (gi < R) {
                // exact sequential path (edge rows; ref-rounding bit-match)
#pragma unroll
                for (int e = 0; e < 4; ++e) {
                    vI[e]  = __fsub_rn(__fadd_rn(vI[e],  in_[e]), io_[e]);
                    vP[e]  = __fsub_rn(__fadd_rn(vP[e],  pn_[e]), po_[e]);
                    vIP[e] = __fsub_rn(__fadd_rn(vIP[e], __fmul_rn(in_[e], pn_[e])),
                                       __fmul_rn(io_[e], po_[e]));
                    vII[e] = __fsub_rn(__fadd_rn(vII[e], __fmul_rn(in_[e], in_[e])),
                                       __fmul_rn(io_[e], io_[e]));
                }
            } else {
#pragma unroll
                for (int e = 0; e < 4; ++e) {
                    vI[e]  = __fsub_rn(__fadd_rn(vI[e],  in_[e]), io_[e]);
                    vP[e]  = __fsub_rn(__fadd_rn(vP[e],  pn_[e]), po_[e]);
                    vIP[e] = fmaf(in_[e], pn_[e], fmaf(-io_[e], po_[e], vIP[e]));
                    vII[e] = fmaf(in_[e], in_[e], fmaf(-io_[e], io_[e], vII[e]));
                }
            }
        }
        if (hasHalo) {
            // halo feeds only cols >= 108 (well-conditioned): FMA always
            const float in_[4] = {HIn.x, HIn.y, HIn.z, HIn.w};
            const float pn_[4] = {HPn.x, HPn.y, HPn.z, HPn.w};
            const float io_[4] = {HIo.x, HIo.y, HIo.z, HIo.w};
            const float po_[4] = {HPo.x, HPo.y, HPo.z, HPo.w};
#pragma unroll
            for (int e = 0; e < 4; ++e) {
                hI[e]  = __fsub_rn(__fadd_rn(hI[e],  in_[e]), io_[e]);
                hP[e]  = __fsub_rn(__fadd_rn(hP[e],  pn_[e]), po_[e]);
                hIP[e] = fmaf(in_[e], pn_[e], fmaf(-io_[e], po_[e], hIP[e]));
                hII[e] = fmaf(in_[e], in_[e], fmaf(-io_[e], io_[e], hII[e]));
            }
        }

        if (gi >= r0) {
            float w0[4], w1[4], w2[4], w3[4];
            hwindow(vI,  hI,  hasHalo, lane, w0);
            hwindow(vP,  hP,  hasHalo, lane, w1);
            hwindow(vIP, hIP, hasHalo, lane, w2);
            hwindow(vII, hII, hasHalo, lane, w3);

            const bool divpath = (gi + 1 < R) || (!hasHalo && lane < 5);
            float A_[4], b_[4];
            if (divpath) {
                const float Nrf = (gi + 1 < R) ? (float)(gi + 1) : 20.0f;
#pragma unroll
                for (int e = 0; e < 4; ++e) {
                    const int colp1 = c0 + lane * 4 + e + 1;
                    const float Ncf = (colp1 < R) ? (float)colp1 : 20.0f;
                    const float Nf = __fmul_rn(Nrf, Ncf);
                    const float m0 = __fdiv_rn(w0[e], Nf);
                    const float m1 = __fdiv_rn(w1[e], Nf);
                    const float m2 = __fdiv_rn(w2[e], Nf);
                    const float m3 = __fdiv_rn(w3[e], Nf);
                    const float cov = __fsub_rn(m2, __fmul_rn(m0, m1));
                    const float var = __fsub_rn(m3, __fmul_rn(m0, m0));
                    A_[e] = __fdiv_rn(cov, __fadd_rn(var, 1e-8f));
                    b_[e] = __fsub_rn(m1, __fmul_rn(A_[e], m0));
                }
            } else {
#pragma unroll
                for (int e = 0; e < 4; ++e) {
                    const float m0 = w0[e] * inv400;
                    const float m1 = w1[e] * inv400;
                    const float m2 = w2[e] * inv400;
                    const float m3 = w3[e] * inv400;
                    const float cov = fmaf(-m0, m1, m2);
                    const float var = fmaf(-m0, m0, m3);
                    const float A = __fdividef(cov, var + 1e-8f);
                    A_[e] = A;
                    b_[e] = fmaf(-A, m0, m1);
                }
            }
            const int sbase = gi * (Wn / 2) + (c0 >> 1) + lane * 2;
            __stcs(AB4 + sbase,     make_float4(A_[0], b_[0], A_[1], b_[1]));
            __stcs(AB4 + sbase + 1, make_float4(A_[2], b_[2], A_[3], b_[3]));
        }
    }
}

__global__ void __launch_bounds__(TPB, 6)
gf_stage2(const float* __restrict__ gI, float* __restrict__ gQ)
{
    const int lane = threadIdx.x & 31;
    const int wid  = threadIdx.x >> 5;
    const int img  = blockIdx.z;
    const int c0   = (blockIdx.x * 4 + wid) * 128;
    const bool hasHalo = (c0 != 0);
    const int r0 = blockIdx.y * BANDH;
    const int r1 = r0 + BANDH;
    const int gstart = (r0 >= R - 1) ? (r0 - (R - 1)) : 0;
    const int subStart = gstart + R;

    const float4* I4  = (const float4*)(gI + (size_t)img * Hn * Wn);
    const float4* AB4 = g_AB4 + (size_t)img * Hn * (Wn / 2);
    float4* Q4 = (float4*)(gQ + (size_t)img * Hn * Wn);

    const int mi = (c0 >> 2) + lane;
    const int ai = (c0 >> 1) + lane * 2;
    const int hai = ((c0 - 20) >> 1) + lane * 2;

    float vA[4] = {0,0,0,0}, vB[4] = {0,0,0,0};
    float hA[4] = {0,0,0,0}, hB[4] = {0,0,0,0};
    const float inv400 = 1.0f / 400.0f;

    for (int gi = gstart; gi < r1; ++gi) {
        const int abase = gi * (Wn / 2);
        const float4 u0 = AB4[abase + ai];      // reused as 'old' within 20 rows: keep in L2
        const float4 u1 = AB4[abase + ai + 1];
        float4 o0 = make_float4(0.f,0.f,0.f,0.f), o1 = o0;
        float4 hu0 = o0, hu1 = o0, ho0 = o0, ho1 = o0;
        const bool doSub = (gi >= subStart);
        const int obase = (gi - R) * (Wn / 2);
        if (doSub) { o0 = __ldcs(AB4 + obase + ai); o1 = __ldcs(AB4 + obase + ai + 1); }
        if (hasHalo && lane < 5) {
            hu0 = AB4[abase + hai]; hu1 = AB4[abase + hai + 1];
            if (doSub) { ho0 = __ldcs(AB4 + obase + hai); ho1 = __ldcs(AB4 + obase + hai + 1); }
        }

        {
            const float an[4] = {u0.x, u0.z, u1.x, u1.z};
            const float bn[4] = {u0.y, u0.w, u1.y, u1.w};
            const float ao[4] = {o0.x, o0.z, o1.x, o1.z};
            const float bo[4] = {o0.y, o0.w, o1.y, o1.w};
#pragma unroll
            for (int e = 0; e < 4; ++e) {
                vA[e] = __fsub_rn(__fadd_rn(vA[e], an[e]), ao[e]);
                vB[e] = __fsub_rn(__fadd_rn(vB[e], bn[e]), bo[e]);
            }
        }
        if (hasHalo) {
            const float an[4] = {hu0.x, hu0.z, hu1.x, hu1.z};
            const float bn[4] = {hu0.y, hu0.w, hu1.y, hu1.w};
            const float ao[4] = {ho0.x, ho0.z, ho1.x, ho1.z};
            const float bo[4] = {ho0.y, ho0.w, ho1.y, ho1.w};
#pragma unroll
            for (int e = 0; e < 4; ++e) {
                hA[e] = __fsub_rn(__fadd_rn(hA[e], an[e]), ao[e]);
                hB[e] = __fsub_rn(__fadd_rn(hB[e], bn[e]), bo[e]);
            }
        }

        if (gi >= r0) {
            u64t vAB[4], hAB[4], wAB[4];
#pragma unroll
            for (int e = 0; e < 4; ++e) {
                vAB[e] = pk2(vA[e], vB[e]);
                hAB[e] = pk2(hA[e], hB[e]);
            }
            hwindow2(vAB, hAB, hasHalo, lane, wAB);

            const bool divpath = (gi + 1 < R) || (!hasHalo && lane < 5);
            const float4 Iv = __ldcs(I4 + (gi << 8) + mi);
            const float iv_[4] = {Iv.x, Iv.y, Iv.z, Iv.w};
            float q_[4];
            if (divpath) {
                const float Nrf = (gi + 1 < R) ? (float)(gi + 1) : 20.0f;
#pragma unroll
                for (int e = 0; e < 4; ++e) {
                    const int colp1 = c0 + lane * 4 + e + 1;
                    const float Ncf = (colp1 < R) ? (float)colp1 : 20.0f;
                    const float Nf = __fmul_rn(Nrf, Ncf);
                    const float mA = __fdiv_rn(lo2(wAB[e]), Nf);
                    const float mB = __fdiv_rn(hi2(wAB[e]), Nf);
                    q_[e] = __fadd_rn(__fmul_rn(mA, iv_[e]), mB);
                }
            } else {
#pragma unroll
                for (int e = 0; e < 4; ++e) {
                    const float mA = lo2(wAB[e]) * inv400;
                    const float mB = hi2(wAB[e]) * inv400;
                    q_[e] = fmaf(mA, iv_[e], mB);
                }
            }
            __stcs(Q4 + (gi << 8) + mi, make_float4(q_[0], q_[1], q_[2], q_[3]));
        }
    }
}

extern "C" void kernel_launch(void* const* d_in, const int* in_sizes, int n_in,
                              void* d_out, int out_size)
{
    (void)in_sizes; (void)n_in; (void)out_size;
    const float* I = (const float*)d_in[0];
    const float* p = (const float*)d_in[1];
    float* q = (float*)d_out;

    dim3 grid(2, NBAND, NIMG);
    gf_stage1<<<grid, TPB>>>(I, p);
    gf_stage2<<<grid, TPB>>>(I, q);
}

// round 14
// speedup vs baseline: 1.3320x; 1.0523x over previous
#include <cuda_runtime.h>
#include <cuda_fp16.h>

// GuidedFilter, causal box window R=20 (trailing, clamped prefix at edges), H then W.
// Stage1: box{I,p,Ip,I2} -> A,b (scratch, FP16 half2/pixel).  Stage2: box{A,b} -> q.
//
// R14 = R13 with the AB scratch stored as half2 (A,b) per pixel:
//  - scratch traffic halves (write 96 MB, read 96 MB; 20-row re-read window ~2MB => L2-hot)
//  - stage2 AB loads per row: 8 -> 4 (uint4 covers 4 pixels)
//  - precision: |dA|,|db| <= 2^-11 rel, decorrelated across windows -> q err ~1e-5;
//    chaotic edge pixels keep A == 0 exactly (fp32 0 -> fp16 0).
// stage1: scalar hwindow, FMA split, bounds(128,5). stage2: packed hwindow2,
// bounds(128,6). __ldcs on last-touch loads, __stcs on streaming stores.

#define Hn 1024
#define Wn 1024
#define NIMG 24
#define R 20
#define NBAND 16
#define BANDH 64
#define TPB 128

typedef unsigned long long u64t;

// AB scratch: uint4 = 4 pixels x half2(A,b). 24*1024*256*16B = 96 MB.
__device__ uint4 g_ABh[(size_t)NIMG * Hn * (Wn / 4)];

__device__ __forceinline__ u64t pk2(float lo, float hi) {
    u64t r; asm("mov.b64 %0,{%1,%2};" : "=l"(r) : "f"(lo), "f"(hi)); return r;
}
__device__ __forceinline__ float lo2(u64t v) {
    float a; asm("{ .reg .f32 h; mov.b64 {%0,h}, %1; }" : "=f"(a) : "l"(v)); return a;
}
__device__ __forceinline__ float hi2(u64t v) {
    float b; asm("{ .reg .f32 l; mov.b64 {l,%0}, %1; }" : "=f"(b) : "l"(v)); return b;
}
__device__ __forceinline__ u64t add2(u64t a, u64t b) {
    u64t r; asm("add.rn.f32x2 %0,%1,%2;" : "=l"(r) : "l"(a), "l"(b)); return r;
}
__device__ __forceinline__ u64t sub2(u64t a, u64t b) {   // rn(a-b) per field
    u64t r; const u64t n1 = 0xBF800000BF800000ULL;
    asm("fma.rn.f32x2 %0,%1,%2,%3;" : "=l"(r) : "l"(b), "l"(n1), "l"(a)); return r;
}

__device__ __forceinline__ unsigned int h2u(__half2 h) {
    return *reinterpret_cast<unsigned int*>(&h);
}
__device__ __forceinline__ void upk(unsigned int u, float& a, float& b) {
    __half2 h = *reinterpret_cast<__half2*>(&u);
    float2 f = __half22float2(h);
    a = f.x; b = f.y;
}

// ---------------- scalar hwindow (stage1) ----------------
__device__ __forceinline__ void hwindow(const float v[4], const float hv[4],
                                        bool hasHalo, int lane, float w[4])
{
    const float p0 = v[0];
    const float p1 = __fadd_rn(p0, v[1]);
    const float p2 = __fadd_rn(p1, v[2]);
    const float p3 = __fadd_rn(p2, v[3]);
    const float T  = p3;

    const float t1 = __shfl_up_sync(0xffffffffu, T, 1);
    const float t2 = __shfl_up_sync(0xffffffffu, T, 2);
    const float t3 = __shfl_up_sync(0xffffffffu, T, 3);
    const float t4 = __shfl_up_sync(0xffffffffu, T, 4);
    const float t5 = __shfl_up_sync(0xffffffffu, T, 5);
    const float s0 = __shfl_up_sync(0xffffffffu, p0, 5);
    const float s1 = __shfl_up_sync(0xffffffffu, p1, 5);
    const float s2 = __shfl_up_sync(0xffffffffu, p2, 5);
    const float s3 = t5;                    // p3 == T

    float sumT = 0.0f;
    if (lane >= 1) sumT = __fadd_rn(sumT, t1);
    if (lane >= 2) sumT = __fadd_rn(sumT, t2);
    if (lane >= 3) sumT = __fadd_rn(sumT, t3);
    if (lane >= 4) sumT = __fadd_rn(sumT, t4);
    if (lane >= 5) sumT = __fadd_rn(sumT, t5);

    const float hp0 = hv[0];
    const float hp1 = __fadd_rn(hp0, hv[1]);
    const float hp2 = __fadd_rn(hp1, hv[2]);
    const float hp3 = __fadd_rn(hp2, hv[3]);
    const float d1 = __shfl_down_sync(0xffffffffu, hp3, 1);
    const float d2 = __shfl_down_sync(0xffffffffu, hp3, 2);
    const float d3 = __shfl_down_sync(0xffffffffu, hp3, 3);
    const float d4 = __shfl_down_sync(0xffffffffu, hp3, 4);
    float hs = 0.0f;
    if (lane <= 3) hs = __fadd_rn(hs, d1);
    if (lane <= 2) hs = __fadd_rn(hs, d2);
    if (lane <= 1) hs = __fadd_rn(hs, d3);
    if (lane == 0) hs = __fadd_rn(hs, d4);

    const float hq0 = __fsub_rn(hp3, hp0);
    const float hq1 = __fsub_rn(hp3, hp1);
    const float hq2 = __fsub_rn(hp3, hp2);

    const float c0_ = __fadd_rn(p0, sumT);
    const float c1_ = __fadd_rn(p1, sumT);
    const float c2_ = __fadd_rn(p2, sumT);
    const float c3_ = __fadd_rn(p3, sumT);

    if (lane >= 5) {
        w[0] = __fsub_rn(c0_, s0);
        w[1] = __fsub_rn(c1_, s1);
        w[2] = __fsub_rn(c2_, s2);
        w[3] = __fsub_rn(c3_, s3);
    } else if (hasHalo) {
        w[0] = __fadd_rn(__fadd_rn(c0_, hs), hq0);
        w[1] = __fadd_rn(__fadd_rn(c1_, hs), hq1);
        w[2] = __fadd_rn(__fadd_rn(c2_, hs), hq2);
        w[3] = __fadd_rn(c3_, hs);
    } else {
        w[0] = c0_;
        w[1] = c1_;
        w[2] = c2_;
        w[3] = c3_;
    }
}

// ---------------- packed hwindow (stage2) ----------------
__device__ __forceinline__ void hwindow2(const u64t v[4], const u64t hv[4],
                                         bool hasHalo, int lane, u64t w[4])
{
    const u64t p0 = v[0];
    const u64t p1 = add2(p0, v[1]);
    const u64t p2 = add2(p1, v[2]);
    const u64t p3 = add2(p2, v[3]);
    const u64t T  = p3;

    const u64t t1 = __shfl_up_sync(0xffffffffu, T, 1);
    const u64t t2 = __shfl_up_sync(0xffffffffu, T, 2);
    const u64t t3 = __shfl_up_sync(0xffffffffu, T, 3);
    const u64t t4 = __shfl_up_sync(0xffffffffu, T, 4);
    const u64t t5 = __shfl_up_sync(0xffffffffu, T, 5);
    const u64t s0 = __shfl_up_sync(0xffffffffu, p0, 5);
    const u64t s1 = __shfl_up_sync(0xffffffffu, p1, 5);
    const u64t s2 = __shfl_up_sync(0xffffffffu, p2, 5);
    const u64t s3 = t5;

    u64t sumT = 0ULL;
    if (lane >= 1) sumT = add2(sumT, t1);
    if (lane >= 2) sumT = add2(sumT, t2);
    if (lane >= 3) sumT = add2(sumT, t3);
    if (lane >= 4) sumT = add2(sumT, t4);
    if (lane >= 5) sumT = add2(sumT, t5);

    const u64t hp0 = hv[0];
    const u64t hp1 = add2(hp0, hv[1]);
    const u64t hp2 = add2(hp1, hv[2]);
    const u64t hp3 = add2(hp2, hv[3]);
    const u64t d1 = __shfl_down_sync(0xffffffffu, hp3, 1);
    const u64t d2 = __shfl_down_sync(0xffffffffu, hp3, 2);
    const u64t d3 = __shfl_down_sync(0xffffffffu, hp3, 3);
    const u64t d4 = __shfl_down_sync(0xffffffffu, hp3, 4);
    u64t hs = 0ULL;
    if (lane <= 3) hs = add2(hs, d1);
    if (lane <= 2) hs = add2(hs, d2);
    if (lane <= 1) hs = add2(hs, d3);
    if (lane == 0) hs = add2(hs, d4);

    const u64t hq0 = sub2(hp3, hp0);
    const u64t hq1 = sub2(hp3, hp1);
    const u64t hq2 = sub2(hp3, hp2);

    const u64t c0_ = add2(p0, sumT);
    const u64t c1_ = add2(p1, sumT);
    const u64t c2_ = add2(p2, sumT);
    const u64t c3_ = add2(p3, sumT);

    if (lane >= 5) {
        w[0] = sub2(c0_, s0);
        w[1] = sub2(c1_, s1);
        w[2] = sub2(c2_, s2);
        w[3] = sub2(c3_, s3);
    } else if (hasHalo) {
        w[0] = add2(add2(c0_, hs), hq0);
        w[1] = add2(add2(c1_, hs), hq1);
        w[2] = add2(add2(c2_, hs), hq2);
        w[3] = add2(c3_, hs);
    } else {
        w[0] = c0_;
        w[1] = c1_;
        w[2] = c2_;
        w[3] = c3_;
    }
}

__global__ void __launch_bounds__(TPB, 5)
gf_stage1(const float* __restrict__ gI, const float* __restrict__ gP)
{
    const int lane = threadIdx.x & 31;
    const int wid  = threadIdx.x >> 5;
    const int img  = blockIdx.z;
    const int c0   = (blockIdx.x * 4 + wid) * 128;
    const bool hasHalo = (c0 != 0);
    const int r0 = blockIdx.y * BANDH;
    const int r1 = r0 + BANDH;
    const int gstart = (r0 >= R - 1) ? (r0 - (R - 1)) : 0;
    const int subStart = gstart + R;

    const float4* I4  = (const float4*)(gI + (size_t)img * Hn * Wn);
    const float4* P4  = (const float4*)(gP + (size_t)img * Hn * Wn);
    uint4* ABu = g_ABh + (size_t)img * Hn * (Wn / 4);

    const int mi = (c0 >> 2) + lane;
    const int hi = ((c0 - 20) >> 2) + lane;

    float vI[4]  = {0,0,0,0}, vP[4]  = {0,0,0,0};
    float vIP[4] = {0,0,0,0}, vII[4] = {0,0,0,0};
    float hI[4]  = {0,0,0,0}, hP[4]  = {0,0,0,0};
    float hIP[4] = {0,0,0,0}, hII[4] = {0,0,0,0};
    const float inv400 = 1.0f / 400.0f;

    for (int gi = gstart; gi < r1; ++gi) {
        const int rbase = gi << 8;
        const float4 In = I4[rbase + mi];       // reused as 'old' within 20 rows: keep in L2
        const float4 Pn = P4[rbase + mi];
        float4 Io = make_float4(0.f,0.f,0.f,0.f), Po = Io;
        float4 HIn = Io, HPn = Io, HIo = Io, HPo = Io;
        const bool doSub = (gi >= subStart);
        const int obase = (gi - R) << 8;
        if (doSub) { Io = __ldcs(I4 + obase + mi); Po = __ldcs(P4 + obase + mi); }
        if (hasHalo && lane < 5) {
            HIn = I4[rbase + hi]; HPn = P4[rbase + hi];
            if (doSub) { HIo = __ldcs(I4 + obase + hi); HPo = __ldcs(P4 + obase + hi); }
        }

        {
            const float in_[4] = {In.x, In.y, In.z, In.w};
            const float pn_[4] = {Pn.x, Pn.y, Pn.z, Pn.w};
            const float io_[4] = {Io.x, Io.y, Io.z, Io.w};
            const float po_[4] = {Po.x, Po.y, Po.z, Po.w};
            if (gi < R) {
                // exact sequential path (edge rows; keeps A==0 at chaotic pixels)
#pragma unroll
                for (int e = 0; e < 4; ++e) {
                    vI[e]  = __fsub_rn(__fadd_rn(vI[e],  in_[e]), io_[e]);
                    vP[e]  = __fsub_rn(__fadd_rn(vP[e],  pn_[e]), po_[e]);
                    vIP[e] = __fsub_rn(__fadd_rn(vIP[e], __fmul_rn(in_[e], pn_[e])),
                                       __fmul_rn(io_[e], po_[e]));
                    vII[e] = __fsub_rn(__fadd_rn(vII[e], __fmul_rn(in_[e], in_[e])),
                                       __fmul_rn(io_[e], io_[e]));
                }
            } else {
#pragma unroll
                for (int e = 0; e < 4; ++e) {
                    vI[e]  = __fsub_rn(__fadd_rn(vI[e],  in_[e]), io_[e]);
                    vP[e]  = __fsub_rn(__fadd_rn(vP[e],  pn_[e]), po_[e]);
                    vIP[e] = fmaf(in_[e], pn_[e], fmaf(-io_[e], po_[e], vIP[e]));
                    vII[e] = fmaf(in_[e], in_[e], fmaf(-io_[e], io_[e], vII[e]));
                }
            }
        }
        if (hasHalo) {
            const float in_[4] = {HIn.x, HIn.y, HIn.z, HIn.w};
            const float pn_[4] = {HPn.x, HPn.y, HPn.z, HPn.w};
            const float io_[4] = {HIo.x, HIo.y, HIo.z, HIo.w};
            const float po_[4] = {HPo.x, HPo.y, HPo.z, HPo.w};
#pragma unroll
            for (int e = 0; e < 4; ++e) {
                hI[e]  = __fsub_rn(__fadd_rn(hI[e],  in_[e]), io_[e]);
                hP[e]  = __fsub_rn(__fadd_rn(hP[e],  pn_[e]), po_[e]);
                hIP[e] = fmaf(in_[e], pn_[e], fmaf(-io_[e], po_[e], hIP[e]));
                hII[e] = fmaf(in_[e], in_[e], fmaf(-io_[e], io_[e], hII[e]));
            }
        }

        if (gi >= r0) {
            float w0[4], w1[4], w2[4], w3[4];
            hwindow(vI,  hI,  hasHalo, lane, w0);
            hwindow(vP,  hP,  hasHalo, lane, w1);
            hwindow(vIP, hIP, hasHalo, lane, w2);
            hwindow(vII, hII, hasHalo, lane, w3);

            const bool divpath = (gi + 1 < R) || (!hasHalo && lane < 5);
            float A_[4], b_[4];
            if (divpath) {
                const float Nrf = (gi + 1 < R) ? (float)(gi + 1) : 20.0f;
#pragma unroll
                for (int e = 0; e < 4; ++e) {
                    const int colp1 = c0 + lane * 4 + e + 1;
                    const float Ncf = (colp1 < R) ? (float)colp1 : 20.0f;
                    const float Nf = __fmul_rn(Nrf, Ncf);
                    const float m0 = __fdiv_rn(w0[e], Nf);
                    const float m1 = __fdiv_rn(w1[e], Nf);
                    const float m2 = __fdiv_rn(w2[e], Nf);
                    const float m3 = __fdiv_rn(w3[e], Nf);
                    const float cov = __fsub_rn(m2, __fmul_rn(m0, m1));
                    const float var = __fsub_rn(m3, __fmul_rn(m0, m0));
                    A_[e] = __fdiv_rn(cov, __fadd_rn(var, 1e-8f));
                    b_[e] = __fsub_rn(m1, __fmul_rn(A_[e], m0));
                }
            } else {
#pragma unroll
                for (int e = 0; e < 4; ++e) {
                    const float m0 = w0[e] * inv400;
                    const float m1 = w1[e] * inv400;
                    const float m2 = w2[e] * inv400;
                    const float m3 = w3[e] * inv400;
                    const float cov = fmaf(-m0, m1, m2);
                    const float var = fmaf(-m0, m0, m3);
                    const float A = __fdividef(cov, var + 1e-8f);
                    A_[e] = A;
                    b_[e] = fmaf(-A, m0, m1);
                }
            }
            uint4 st;
            st.x = h2u(__floats2half2_rn(A_[0], b_[0]));
            st.y = h2u(__floats2half2_rn(A_[1], b_[1]));
            st.z = h2u(__floats2half2_rn(A_[2], b_[2]));
            st.w = h2u(__floats2half2_rn(A_[3], b_[3]));
            __stcs(ABu + (gi << 8) + mi, st);
        }
    }
}

__global__ void __launch_bounds__(TPB, 6)
gf_stage2(const float* __restrict__ gI, float* __restrict__ gQ)
{
    const int lane = threadIdx.x & 31;
    const int wid  = threadIdx.x >> 5;
    const int img  = blockIdx.z;
    const int c0   = (blockIdx.x * 4 + wid) * 128;
    const bool hasHalo = (c0 != 0);
    const int r0 = blockIdx.y * BANDH;
    const int r1 = r0 + BANDH;
    const int gstart = (r0 >= R - 1) ? (r0 - (R - 1)) : 0;
    const int subStart = gstart + R;

    const float4* I4  = (const float4*)(gI + (size_t)img * Hn * Wn);
    const uint4* ABu = g_ABh + (size_t)img * Hn * (Wn / 4);
    float4* Q4 = (float4*)(gQ + (size_t)img * Hn * Wn);

    const int mi = (c0 >> 2) + lane;
    const int hi = ((c0 - 20) >> 2) + lane;

    float vA[4] = {0,0,0,0}, vB[4] = {0,0,0,0};
    float hA[4] = {0,0,0,0}, hB[4] = {0,0,0,0};
    const float inv400 = 1.0f / 400.0f;
    const uint4 zu4 = make_uint4(0u, 0u, 0u, 0u);   // half2(0,0) pairs

    for (int gi = gstart; gi < r1; ++gi) {
        const int rbase = gi << 8;
        const uint4 u = ABu[rbase + mi];        // reused as 'old' within 20 rows: keep in L2
        uint4 o = zu4, hu = zu4, ho = zu4;
        const bool doSub = (gi >= subStart);
        const int obase = (gi - R) << 8;
        if (doSub) o = __ldcs(ABu + obase + mi);
        if (hasHalo && lane < 5) {
            hu = ABu[rbase + hi];
            if (doSub) ho = __ldcs(ABu + obase + hi);
        }

        {
            float an[4], bn[4], ao[4], bo[4];
            upk(u.x, an[0], bn[0]); upk(u.y, an[1], bn[1]);
            upk(u.z, an[2], bn[2]); upk(u.w, an[3], bn[3]);
            upk(o.x, ao[0], bo[0]); upk(o.y, ao[1], bo[1]);
            upk(o.z, ao[2], bo[2]); upk(o.w, ao[3], bo[3]);
#pragma unroll
            for (int e = 0; e < 4; ++e) {
                vA[e] = __fsub_rn(__fadd_rn(vA[e], an[e]), ao[e]);
                vB[e] = __fsub_rn(__fadd_rn(vB[e], bn[e]), bo[e]);
            }
        }
        if (hasHalo) {
            float an[4], bn[4], ao[4], bo[4];
            upk(hu.x, an[0], bn[0]); upk(hu.y, an[1], bn[1]);
            upk(hu.z, an[2], bn[2]); upk(hu.w, an[3], bn[3]);
            upk(ho.x, ao[0], bo[0]); upk(ho.y, ao[1], bo[1]);
            upk(ho.z, ao[2], bo[2]); upk(ho.w, ao[3], bo[3]);
#pragma unroll
            for (int e = 0; e < 4; ++e) {
                hA[e] = __fsub_rn(__fadd_rn(hA[e], an[e]), ao[e]);
                hB[e] = __fsub_rn(__fadd_rn(hB[e], bn[e]), bo[e]);
            }
        }

        if (gi >= r0) {
            u64t vAB[4], hAB[4], wAB[4];
#pragma unroll
            for (int e = 0; e < 4; ++e) {
                vAB[e] = pk2(vA[e], vB[e]);
                hAB[e] = pk2(hA[e], hB[e]);
            }
            hwindow2(vAB, hAB, hasHalo, lane, wAB);

            const bool divpath = (gi + 1 < R) || (!hasHalo && lane < 5);
            const float4 Iv = __ldcs(I4 + rbase + mi);
            const float iv_[4] = {Iv.x, Iv.y, Iv.z, Iv.w};
            float q_[4];
            if (divpath) {
                const float Nrf = (gi + 1 < R) ? (float)(gi + 1) : 20.0f;
#pragma unroll
                for (int e = 0; e < 4; ++e) {
                    const int colp1 = c0 + lane * 4 + e + 1;
                    const float Ncf = (colp1 < R) ? (float)colp1 : 20.0f;
                    const float Nf = __fmul_rn(Nrf, Ncf);
                    const float mA = __fdiv_rn(lo2(wAB[e]), Nf);
                    const float mB = __fdiv_rn(hi2(wAB[e]), Nf);
                    q_[e] = __fadd_rn(__fmul_rn(mA, iv_[e]), mB);
                }
            } else {
#pragma unroll
                for (int e = 0; e < 4; ++e) {
                    const float mA = lo2(wAB[e]) * inv400;
                    const float mB = hi2(wAB[e]) * inv400;
                    q_[e] = fmaf(mA, iv_[e], mB);
                }
            }
            __stcs(Q4 + rbase + mi, make_float4(q_[0], q_[1], q_[2], q_[3]));
        }
    }
}

extern "C" void kernel_launch(void* const* d_in, const int* in_sizes, int n_in,
                              void* d_out, int out_size)
{
    (void)in_sizes; (void)n_in; (void)out_size;
    const float* I = (const float*)d_in[0];
    const float* p = (const float*)d_in[1];
    float* q = (float*)d_out;

    dim3 grid(2, NBAND, NIMG);
    gf_stage1<<<grid, TPB>>>(I, p);
    gf_stage2<<<grid, TPB>>>(I, q);
}

// round 15
// speedup vs baseline: 1.5176x; 1.1394x over previous
#include <cuda_runtime.h>
#include <cuda_fp16.h>

// GuidedFilter, causal box window R=20 (trailing, clamped prefix at edges), H then W.
// Stage1: box{I,p,Ip,I2} -> A,b (fp16 half2 scratch).  Stage2: box{A,b} -> q.
//
// R15: overlapped warp tiling. Each warp loads 128 contiguous cols (4/lane,
// float4) and OUTPUTS 108 (lanes 0-4 are the in-warp halo). Width-20 window ==
// shfl_up(prefix,5) from live lanes: no redundant halo accumulators, no halo
// loads, no halo section in the window. 10 warps (TPB=320) cover 1024 cols;
// grid = NBAND x NIMG (384 CTAs, 3840 warps).
// Warp 0: lanes 0-4 load zeros -> clamped prefix falls out exactly; cols 0-3
// (critical N<=4 set) are lane 5 with an exact sequential in-lane prefix.
// Exact division for rows<19 and cols<20; fp16 scratch as in R14.

#define Hn 1024
#define Wn 1024
#define NIMG 24
#define R 20
#define NBAND 16
#define BANDH 64
#define TPB 320

// AB scratch: uint4 = 4 pixels x half2(A,b). 96 MB.
__device__ uint4 g_ABh[(size_t)NIMG * Hn * (Wn / 4)];

__device__ __forceinline__ unsigned int h2u(__half2 h) {
    return *reinterpret_cast<unsigned int*>(&h);
}
__device__ __forceinline__ void upk(unsigned int u, float& a, float& b) {
    __half2 h = *reinterpret_cast<__half2*>(&u);
    float2 f = __half22float2(h);
    a = f.x; b = f.y;
}

// Width-20 window, 4 elems/lane, subtrahend 5 lanes up. Valid for lane >= 5.
__device__ __forceinline__ void hwin(const float v[4], int lane, float w[4])
{
    const float p0 = v[0];
    const float p1 = __fadd_rn(p0, v[1]);
    const float p2 = __fadd_rn(p1, v[2]);
    const float p3 = __fadd_rn(p2, v[3]);
    const float T  = p3;

    const float t1 = __shfl_up_sync(0xffffffffu, T, 1);
    const float t2 = __shfl_up_sync(0xffffffffu, T, 2);
    const float t3 = __shfl_up_sync(0xffffffffu, T, 3);
    const float t4 = __shfl_up_sync(0xffffffffu, T, 4);
    const float t5 = __shfl_up_sync(0xffffffffu, T, 5);
    const float s0 = __shfl_up_sync(0xffffffffu, p0, 5);
    const float s1 = __shfl_up_sync(0xffffffffu, p1, 5);
    const float s2 = __shfl_up_sync(0xffffffffu, p2, 5);
    const float s3 = t5;                  // p3 == T

    float sumT = 0.0f;
    sumT = __fadd_rn(sumT, t1);           // lanes >= 5 always have 5 valid lanes above
    sumT = __fadd_rn(sumT, t2);
    sumT = __fadd_rn(sumT, t3);
    sumT = __fadd_rn(sumT, t4);
    sumT = __fadd_rn(sumT, t5);

    w[0] = __fsub_rn(__fadd_rn(p0, sumT), s0);
    w[1] = __fsub_rn(__fadd_rn(p1, sumT), s1);
    w[2] = __fsub_rn(__fadd_rn(p2, sumT), s2);
    w[3] = __fsub_rn(__fadd_rn(p3, sumT), s3);
}

__global__ void __launch_bounds__(TPB, 2)
gf_stage1(const float* __restrict__ gI, const float* __restrict__ gP)
{
    const int lane = threadIdx.x & 31;
    const int j    = threadIdx.x >> 5;        // warp 0..9
    const int band = blockIdx.x;
    const int img  = blockIdx.y;

    const int mi   = 27 * j - 5 + lane;       // float4 index of this lane's 4 cols
    const bool inc = (mi >= 0) && (mi < 256); // load guard
    const bool isOut = (lane >= 5) && (mi < 256);
    const int col0 = mi * 4;                  // first col (valid when isOut)
    const bool strip0 = (j == 0);

    const int r0 = band * BANDH;
    const int r1 = r0 + BANDH;
    const int gstart = (r0 >= R - 1) ? (r0 - (R - 1)) : 0;
    const int subStart = gstart + R;

    const float4* I4 = (const float4*)(gI + (size_t)img * Hn * Wn);
    const float4* P4 = (const float4*)(gP + (size_t)img * Hn * Wn);
    uint4* ABu = g_ABh + (size_t)img * Hn * (Wn / 4);

    float vI[4]  = {0,0,0,0}, vP[4]  = {0,0,0,0};
    float vIP[4] = {0,0,0,0}, vII[4] = {0,0,0,0};
    const float inv400 = 1.0f / 400.0f;
    const float4 zf4 = make_float4(0.f,0.f,0.f,0.f);

    for (int gi = gstart; gi < r1; ++gi) {
        const int rbase = gi << 8;
        float4 In = zf4, Pn = zf4, Io = zf4, Po = zf4;
        const bool doSub = (gi >= subStart);
        if (inc) {
            In = I4[rbase + mi];              // re-read as 'old' within 20 rows: keep in L2
            Pn = P4[rbase + mi];
            if (doSub) {
                const int obase = (gi - R) << 8;
                Io = __ldcs(I4 + obase + mi);
                Po = __ldcs(P4 + obase + mi);
            }
        }

        {
            const float in_[4] = {In.x, In.y, In.z, In.w};
            const float pn_[4] = {Pn.x, Pn.y, Pn.z, Pn.w};
            const float io_[4] = {Io.x, Io.y, Io.z, Io.w};
            const float po_[4] = {Po.x, Po.y, Po.z, Po.w};
            if (gi < R) {
                // exact sequential path (edge rows; ref-rounding bit-match)
#pragma unroll
                for (int e = 0; e < 4; ++e) {
                    vI[e]  = __fsub_rn(__fadd_rn(vI[e],  in_[e]), io_[e]);
                    vP[e]  = __fsub_rn(__fadd_rn(vP[e],  pn_[e]), po_[e]);
                    vIP[e] = __fsub_rn(__fadd_rn(vIP[e], __fmul_rn(in_[e], pn_[e])),
                                       __fmul_rn(io_[e], po_[e]));
                    vII[e] = __fsub_rn(__fadd_rn(vII[e], __fmul_rn(in_[e], in_[e])),
                                       __fmul_rn(io_[e], io_[e]));
                }
            } else {
#pragma unroll
                for (int e = 0; e < 4; ++e) {
                    vI[e]  = __fsub_rn(__fadd_rn(vI[e],  in_[e]), io_[e]);
                    vP[e]  = __fsub_rn(__fadd_rn(vP[e],  pn_[e]), po_[e]);
                    vIP[e] = fmaf(in_[e], pn_[e], fmaf(-io_[e], po_[e], vIP[e]));
                    vII[e] = fmaf(in_[e], in_[e], fmaf(-io_[e], io_[e], vII[e]));
                }
            }
        }

        if (gi >= r0) {
            float w0[4], w1[4], w2[4], w3[4];
            hwin(vI,  lane, w0);
            hwin(vP,  lane, w1);
            hwin(vIP, lane, w2);
            hwin(vII, lane, w3);

            if (isOut) {
                const bool divpath = (gi + 1 < R) || (strip0 && lane < 10);
                float A_[4], b_[4];
                if (divpath) {
                    const float Nrf = (gi + 1 < R) ? (float)(gi + 1) : 20.0f;
#pragma unroll
                    for (int e = 0; e < 4; ++e) {
                        const int colp1 = col0 + e + 1;
                        const float Ncf = (colp1 < R) ? (float)colp1 : 20.0f;
                        const float Nf = __fmul_rn(Nrf, Ncf);
                        const float m0 = __fdiv_rn(w0[e], Nf);
                        const float m1 = __fdiv_rn(w1[e], Nf);
                        const float m2 = __fdiv_rn(w2[e], Nf);
                        const float m3 = __fdiv_rn(w3[e], Nf);
                        const float cov = __fsub_rn(m2, __fmul_rn(m0, m1));
                        const float var = __fsub_rn(m3, __fmul_rn(m0, m0));
                        A_[e] = __fdiv_rn(cov, __fadd_rn(var, 1e-8f));
                        b_[e] = __fsub_rn(m1, __fmul_rn(A_[e], m0));
                    }
                } else {
#pragma unroll
                    for (int e = 0; e < 4; ++e) {
                        const float m0 = w0[e] * inv400;
                        const float m1 = w1[e] * inv400;
                        const float m2 = w2[e] * inv400;
                        const float m3 = w3[e] * inv400;
                        const float cov = fmaf(-m0, m1, m2);
                        const float var = fmaf(-m0, m0, m3);
                        const float A = __fdividef(cov, var + 1e-8f);
                        A_[e] = A;
                        b_[e] = fmaf(-A, m0, m1);
                    }
                }
                uint4 st;
                st.x = h2u(__floats2half2_rn(A_[0], b_[0]));
                st.y = h2u(__floats2half2_rn(A_[1], b_[1]));
                st.z = h2u(__floats2half2_rn(A_[2], b_[2]));
                st.w = h2u(__floats2half2_rn(A_[3], b_[3]));
                __stcs(ABu + rbase + mi, st);
            }
        }
    }
}

__global__ void __launch_bounds__(TPB, 2)
gf_stage2(const float* __restrict__ gI, float* __restrict__ gQ)
{
    const int lane = threadIdx.x & 31;
    const int j    = threadIdx.x >> 5;
    const int band = blockIdx.x;
    const int img  = blockIdx.y;

    const int mi   = 27 * j - 5 + lane;
    const bool inc = (mi >= 0) && (mi < 256);
    const bool isOut = (lane >= 5) && (mi < 256);
    const int col0 = mi * 4;
    const bool strip0 = (j == 0);

    const int r0 = band * BANDH;
    const int r1 = r0 + BANDH;
    const int gstart = (r0 >= R - 1) ? (r0 - (R - 1)) : 0;
    const int subStart = gstart + R;

    const float4* I4 = (const float4*)(gI + (size_t)img * Hn * Wn);
    const uint4* ABu = g_ABh + (size_t)img * Hn * (Wn / 4);
    float4* Q4 = (float4*)(gQ + (size_t)img * Hn * Wn);

    float vA[4] = {0,0,0,0}, vB[4] = {0,0,0,0};
    const float inv400 = 1.0f / 400.0f;
    const uint4 zu4 = make_uint4(0u,0u,0u,0u);    // half2(0,0)

    for (int gi = gstart; gi < r1; ++gi) {
        const int rbase = gi << 8;
        uint4 u = zu4, o = zu4;
        const bool doSub = (gi >= subStart);
        if (inc) {
            u = ABu[rbase + mi];              // re-read as 'old' within 20 rows: keep in L2
            if (doSub) o = __ldcs(ABu + ((gi - R) << 8) + mi);
        }

        {
            float an[4], bn[4], ao[4], bo[4];
            upk(u.x, an[0], bn[0]); upk(u.y, an[1], bn[1]);
            upk(u.z, an[2], bn[2]); upk(u.w, an[3], bn[3]);
            upk(o.x, ao[0], bo[0]); upk(o.y, ao[1], bo[1]);
            upk(o.z, ao[2], bo[2]); upk(o.w, ao[3], bo[3]);
#pragma unroll
            for (int e = 0; e < 4; ++e) {
                vA[e] = __fsub_rn(__fadd_rn(vA[e], an[e]), ao[e]);
                vB[e] = __fsub_rn(__fadd_rn(vB[e], bn[e]), bo[e]);
            }
        }

        if (gi >= r0) {
            float wA[4], wB[4];
            hwin(vA, lane, wA);
            hwin(vB, lane, wB);

            if (isOut) {
                const bool divpath = (gi + 1 < R) || (strip0 && lane < 10);
                const float4 Iv = __ldcs(I4 + rbase + mi);
                const float iv_[4] = {Iv.x, Iv.y, Iv.z, Iv.w};
                float q_[4];
                if (divpath) {
                    const float Nrf = (gi + 1 < R) ? (float)(gi + 1) : 20.0f;
#pragma unroll
                    for (int e = 0; e < 4; ++e) {
                        const int colp1 = col0 + e + 1;
                        const float Ncf = (colp1 < R) ? (float)colp1 : 20.0f;
                        const float Nf = __fmul_rn(Nrf, Ncf);
                        const float mA = __fdiv_rn(wA[e], Nf);
                        const float mB = __fdiv_rn(wB[e], Nf);
                        q_[e] = __fadd_rn(__fmul_rn(mA, iv_[e]), mB);
                    }
                } else {
#pragma unroll
                    for (int e = 0; e < 4; ++e) {
                        const float mA = wA[e] * inv400;
                        const float mB = wB[e] * inv400;
                        q_[e] = fmaf(mA, iv_[e], mB);
                    }
                }
                __stcs(Q4 + rbase + mi, make_float4(q_[0], q_[1], q_[2], q_[3]));
            }
        }
    }
}

extern "C" void kernel_launch(void* const* d_in, const int* in_sizes, int n_in,
                              void* d_out, int out_size)
{
    (void)in_sizes; (void)n_in; (void)out_size;
    const float* I = (const float*)d_in[0];
    const float* p = (const float*)d_in[1];
    float* q = (float*)d_out;

    dim3 grid(NBAND, NIMG);     // 10 warps per CTA cover all 1024 cols
    gf_stage1<<<grid, TPB>>>(I, p);
    gf_stage2<<<grid, TPB>>>(I, q);
}